// round 13
// baseline (speedup 1.0000x reference)
#include <cuda_runtime.h>
#include <cstdint>

// Problem constants (fixed by the reference: B=2, G=64)
constexpr int G3      = 64 * 64 * 64;   // 262144 voxels per batch
constexpr int NB      = 2;
constexpr int THREADS = 256;
constexpr int PLANE_B = THREADS * 8;    // 2048 B: one output plane per CTA

// Packed f32x2 ops (PTX-only; ptxas never auto-fuses FFMA2 from C++).
__device__ __forceinline__ uint64_t fma2(uint64_t a, uint64_t b, uint64_t c) {
    uint64_t d;
    asm("fma.rn.f32x2 %0, %1, %2, %3;" : "=l"(d) : "l"(a), "l"(b), "l"(c));
    return d;
}
__device__ __forceinline__ uint64_t mul2(uint64_t a, uint64_t b) {
    uint64_t d;
    asm("mul.rn.f32x2 %0, %1, %2;" : "=l"(d) : "l"(a), "l"(b));
    return d;
}
// Un-hoistable shared load (volatile is load-bearing: plain loads let ptxas
// hoist all 81 C0 words into ~162 regs -> spills; R6/R8 evidence).
__device__ __forceinline__ uint64_t lds64(uint32_t saddr) {
    uint64_t d;
    asm volatile("ld.shared.b64 %0, [%1];" : "=l"(d) : "r"(saddr));
    return d;
}
__device__ __forceinline__ void sts64(uint32_t saddr, uint64_t v) {
    asm volatile("st.shared.b64 [%0], %1;" :: "r"(saddr), "l"(v) : "memory");
}
__device__ __forceinline__ uint32_t smem_u32(const void* p) {
    uint32_t r;
    asm("{ .reg .u64 t; cvta.to.shared.u64 t, %1; cvt.u32.u64 %0, t; }"
        : "=r"(r) : "l"(p));
    return r;
}

// C_ijkl[b,v] = sum_{mnop} a[b,m,i,v] a[b,n,j,v] a[b,o,k,v] a[b,p,l,v] C0[mnop]
// R7 compute core (voxel-pair threads, rolled i, C0 via volatile LDS, 2 CTA/SM)
// but the output path is STS -> TMA bulk copy (cp.async.bulk shared->global):
// R9/R10/R11 proved the C0 load path is not the bottleneck; the STG.64 LSU
// dispatch cost (7.75 cyc each, 243/thread) is. STS.64 is ~2-4 cyc and the
// TMA engine does the global writes off the LSU entirely.
__global__ __launch_bounds__(THREADS, 2)
void alphaC0_42C_kernel(const float* __restrict__ a,
                        const float* __restrict__ c0,
                        float* __restrict__ out)
{
    // sc0[m*27+nop] splatted to both f32x2 lanes (direct FFMA2 operand).
    __shared__ uint64_t sc0[81];
    // Double-buffered output staging: 2 x 9 planes x 2KB.
    __shared__ __align__(16) char sbuf[2][9][PLANE_B];

    const int tid = threadIdx.x;
    if (tid < 81) {
        float c = c0[tid];
        float2 cc = make_float2(c, c);
        sc0[tid] = *reinterpret_cast<uint64_t*>(&cc);
    }
    __syncthreads();
    const uint32_t sbase   = smem_u32(sc0);
    const uint32_t bufbase = smem_u32(sbuf);

    // CTA owns 512 consecutive voxels; G3 % 512 == 0 -> never straddles b.
    const uint32_t v2base = (uint32_t)blockIdx.x * (THREADS * 2);
    const int      b      = (v2base >= (uint32_t)G3) ? 1 : 0;
    const uint32_t vbase  = v2base - (uint32_t)b * G3;
    const uint32_t v      = vbase + tid * 2;

    // Load the 3x3 per-voxel matrix a[m][i] for both voxels of the pair.
    const float* ab = a + (long)b * 9 * G3;
    uint64_t A[9];
#pragma unroll
    for (int mi = 0; mi < 9; ++mi)
        A[mi] = *reinterpret_cast<const uint64_t*>(ab + (uint32_t)(mi * G3) + v);

    // Global byte base of this CTA's voxel window in plane 0 of batch b.
    char* gbase = (char*)(out + (long)b * 81 * G3 + vbase);

#pragma unroll 1   // rolled: one-i live set; full unroll spilled (R3)
    for (int i = 0; i < 3; ++i) {
        // Stage 1: T1[n,o,p] = sum_m A[m,i] * C0[m,n,o,p]
        uint64_t T1[27];
#pragma unroll
        for (int nop = 0; nop < 27; ++nop) {
            uint64_t s = mul2(A[0 * 3 + i], lds64(sbase + (uint32_t)(nop * 8)));
            s = fma2(A[1 * 3 + i], lds64(sbase + (uint32_t)((27 + nop) * 8)), s);
            s = fma2(A[2 * 3 + i], lds64(sbase + (uint32_t)((54 + nop) * 8)), s);
            T1[nop] = s;
        }
#pragma unroll
        for (int j = 0; j < 3; ++j) {
            const int g = i * 3 + j;               // group 0..8
            const uint32_t buf = bufbase + (uint32_t)(g & 1) * (9 * PLANE_B);

            // Stage 2: T2[o,p] = sum_n A[n,j] * T1[n,o,p]
            uint64_t T2[9];
#pragma unroll
            for (int op = 0; op < 9; ++op) {
                uint64_t s = mul2(A[0 * 3 + j], T1[op]);
                s = fma2(A[1 * 3 + j], T1[9 + op], s);
                s = fma2(A[2 * 3 + j], T1[18 + op], s);
                T2[op] = s;
            }

            // Before reusing this buffer (used by group g-2), make sure its
            // TMA reads are done: <=1 bulk group pending (group g-1's).
            if (tid == 0)
                asm volatile("cp.async.bulk.wait_group.read 1;" ::: "memory");
            __syncthreads();

#pragma unroll
            for (int k = 0; k < 3; ++k) {
                // Stage 3: T3[p] = sum_o A[o,k] * T2[o,p]
                uint64_t T3[3];
#pragma unroll
                for (int p = 0; p < 3; ++p) {
                    uint64_t s = mul2(A[0 * 3 + k], T2[p]);
                    s = fma2(A[1 * 3 + k], T2[3 + p], s);
                    s = fma2(A[2 * 3 + k], T2[6 + p], s);
                    T3[p] = s;
                }
#pragma unroll
                for (int l = 0; l < 3; ++l) {
                    // Stage 4: C[i,j,k,l] = sum_p A[p,l] * T3[p]
                    uint64_t r = mul2(A[0 * 3 + l], T3[0]);
                    r = fma2(A[1 * 3 + l], T3[1], r);
                    r = fma2(A[2 * 3 + l], T3[2], r);
                    sts64(buf + (uint32_t)((k * 3 + l) * PLANE_B + tid * 8), r);
                }
            }
            __syncthreads();   // all STS of this group visible CTA-wide

            if (tid == 0) {
                asm volatile("fence.proxy.async.shared::cta;" ::: "memory");
#pragma unroll
                for (int kl = 0; kl < 9; ++kl) {
                    const int plane = g * 9 + kl;  // ((i*3+j)*3+k)*3+l
                    char* gdst = gbase + (long)plane * (G3 * 4);
                    asm volatile(
                        "cp.async.bulk.global.shared::cta.bulk_group "
                        "[%0], [%1], %2;"
                        :: "l"(gdst),
                           "r"(buf + (uint32_t)(kl * PLANE_B)),
                           "r"(PLANE_B) : "memory");
                }
                asm volatile("cp.async.bulk.commit_group;" ::: "memory");
            }
        }
    }
    // Pending bulk stores complete/flush at kernel exit (async-proxy writes
    // are made visible at the grid completion boundary).
}

extern "C" void kernel_launch(void* const* d_in, const int* in_sizes, int n_in,
                              void* d_out, int out_size)
{
    const float* a   = (const float*)d_in[0];   // alphatensor (2,3,3,64,64,64)
    const float* c0  = (const float*)d_in[1];   // C0_4 (3,3,3,3)
    float*       out = (float*)d_out;           // (2,3,3,3,3,64,64,64)

    const long total_pairs = (long)NB * G3 / 2;            // 262144
    const int  blocks      = (int)(total_pairs / THREADS); // 1024
    alphaC0_42C_kernel<<<blocks, THREADS>>>(a, c0, out);
}

// round 15
// speedup vs baseline: 1.0008x; 1.0008x over previous
#include <cuda_runtime.h>
#include <cstdint>

// Problem constants (fixed by the reference: B=2, G=64)
constexpr int G3      = 64 * 64 * 64;   // 262144 voxels per batch
constexpr int NB      = 2;
constexpr int THREADS = 192;            // 3 CTAs/SM @ <=112 regs -> 18 warps
constexpr int NPAIRS  = NB * G3 / 2;    // 262144 voxel pairs

// Packed f32x2 ops (PTX-only; ptxas never auto-fuses FFMA2 from C++).
__device__ __forceinline__ uint64_t fma2(uint64_t a, uint64_t b, uint64_t c) {
    uint64_t d;
    asm("fma.rn.f32x2 %0, %1, %2, %3;" : "=l"(d) : "l"(a), "l"(b), "l"(c));
    return d;
}
__device__ __forceinline__ uint64_t mul2(uint64_t a, uint64_t b) {
    uint64_t d;
    asm("mul.rn.f32x2 %0, %1, %2;" : "=l"(d) : "l"(a), "l"(b));
    return d;
}
// Un-hoistable shared load (volatile is load-bearing: plain loads let ptxas
// hoist all 81 C0 words into ~162 regs -> spills; R6/R8 evidence).
__device__ __forceinline__ uint64_t lds64(uint32_t saddr) {
    uint64_t d;
    asm volatile("ld.shared.b64 %0, [%1];" : "=l"(d) : "r"(saddr));
    return d;
}
__device__ __forceinline__ uint32_t smem_u32(const void* p) {
    uint32_t r;
    asm("{ .reg .u64 t; cvta.to.shared.u64 t, %1; cvt.u32.u64 %0, t; }"
        : "=r"(r) : "l"(p));
    return r;
}

// C_ijkl[b,v] = sum_{mnop} a[b,m,i,v] a[b,n,j,v] a[b,o,k,v] a[b,p,l,v] C0[mnop]
// R7 compute core (voxel-pair threads, rolled i, C0 via volatile LDS.64,
// fma.rn.f32x2) reshaped to 192-thread CTAs, 3 CTAs/SM, <=112 regs:
// the register file (64K/SM) is the binding resource — 120 regs capped us at
// 16 warps/SM; trimming 8 regs of ADDRESSING overhead (u32 offsets off one
// 64-bit base) buys an 18th+ warp supply (3x6 warps) without touching the
// 96-reg data live set (A18+T1 54+T2 18+T3 6), so no spill expected.
__global__ __launch_bounds__(THREADS, 3)
void alphaC0_42C_kernel(const float* __restrict__ a,
                        const float* __restrict__ c0,
                        float* __restrict__ out)
{
    // sc0[m*27+nop] splatted to both f32x2 lanes (direct FFMA2 operand).
    __shared__ uint64_t sc0[81];
    if (threadIdx.x < 81) {
        float c = c0[threadIdx.x];
        float2 cc = make_float2(c, c);
        sc0[threadIdx.x] = *reinterpret_cast<uint64_t*>(&cc);
    }
    __syncthreads();
    const uint32_t sbase = smem_u32(sc0);

    // Flattened (b, voxel-pair) index; grid is padded -> guard the tail.
    const uint32_t pair = (uint32_t)blockIdx.x * THREADS + threadIdx.x;
    if (pair >= (uint32_t)NPAIRS) return;
    const uint32_t v2 = pair * 2;
    const int      b  = (v2 >= (uint32_t)G3) ? 1 : 0;
    const uint32_t v  = v2 - (uint32_t)b * G3;

    // Load the 3x3 per-voxel matrix a[m][i] for both voxels of the pair.
    // Single 64-bit base + u32 constant-multiple offsets (max 9 MB, fits u32).
    const float* ab = a + (long)b * 9 * G3 + v;
    uint64_t A[9];
#pragma unroll
    for (int mi = 0; mi < 9; ++mi)
        A[mi] = *reinterpret_cast<const uint64_t*>(ab + (uint32_t)(mi * G3));

    float* ob = out + (long)b * 81 * G3 + v;

#pragma unroll 1   // rolled: one-i live set; full unroll spilled (R3)
    for (int i = 0; i < 3; ++i) {
        const uint64_t Ai0 = A[0 * 3 + i], Ai1 = A[1 * 3 + i], Ai2 = A[2 * 3 + i];
        // Stage 1: T1[n,o,p] = sum_m A[m,i] * C0[m,n,o,p]
        uint64_t T1[27];
#pragma unroll
        for (int nop = 0; nop < 27; ++nop) {
            uint64_t s = mul2(Ai0, lds64(sbase + (uint32_t)(nop * 8)));
            s = fma2(Ai1, lds64(sbase + (uint32_t)((27 + nop) * 8)), s);
            s = fma2(Ai2, lds64(sbase + (uint32_t)((54 + nop) * 8)), s);
            T1[nop] = s;
        }
        // Per-i output base: in-iteration store offsets are compile-time
        // constants (max 26*G3 floats = 27 MB, fits u32).
        float* obi = ob + (uint32_t)(i * 27 * G3);
#pragma unroll
        for (int j = 0; j < 3; ++j) {
            // Stage 2: T2[o,p] = sum_n A[n,j] * T1[n,o,p]
            uint64_t T2[9];
#pragma unroll
            for (int op = 0; op < 9; ++op) {
                uint64_t s = mul2(A[0 * 3 + j], T1[op]);
                s = fma2(A[1 * 3 + j], T1[9 + op], s);
                s = fma2(A[2 * 3 + j], T1[18 + op], s);
                T2[op] = s;
            }
#pragma unroll
            for (int k = 0; k < 3; ++k) {
                // Stage 3: T3[p] = sum_o A[o,k] * T2[o,p]
                uint64_t T3[3];
#pragma unroll
                for (int p = 0; p < 3; ++p) {
                    uint64_t s = mul2(A[0 * 3 + k], T2[p]);
                    s = fma2(A[1 * 3 + k], T2[3 + p], s);
                    s = fma2(A[2 * 3 + k], T2[6 + p], s);
                    T3[p] = s;
                }
#pragma unroll
                for (int l = 0; l < 3; ++l) {
                    // Stage 4: C[i,j,k,l] = sum_p A[p,l] * T3[p]
                    uint64_t r = mul2(A[0 * 3 + l], T3[0]);
                    r = fma2(A[1 * 3 + l], T3[1], r);
                    r = fma2(A[2 * 3 + l], T3[2], r);
                    // Coalesced STG.64, default L2 write-back (streaming
                    // hints hurt — R2 evidence).
                    *reinterpret_cast<uint64_t*>(
                        obi + (uint32_t)(((j * 3 + k) * 3 + l) * G3)) = r;
                }
            }
        }
    }
}

extern "C" void kernel_launch(void* const* d_in, const int* in_sizes, int n_in,
                              void* d_out, int out_size)
{
    const float* a   = (const float*)d_in[0];   // alphatensor (2,3,3,64,64,64)
    const float* c0  = (const float*)d_in[1];   // C0_4 (3,3,3,3)
    float*       out = (float*)d_out;           // (2,3,3,3,3,64,64,64)

    const int blocks = (NPAIRS + THREADS - 1) / THREADS;   // 1366 (padded)
    alphaC0_42C_kernel<<<blocks, THREADS>>>(a, c0, out);
}